// round 9
// baseline (speedup 1.0000x reference)
#include <cuda_runtime.h>
#include <cstdint>

// ---------------- problem constants ----------------
#define NP   1024
#define DD   1024
#define HID  1536

// ---------------- scratch (device globals; no allocations) ----------------
__device__ float g_pr[NP * DD];
__device__ float g_mag[NP * DD];
__device__ float g_hidden[NP * HID];
__device__ float g_wpart[NP * 16];
__device__ float g_wf[NP];
__device__ float g_psum[NP];
__device__ float g_psumsq[NP];
__device__ float g_stats[2];
__device__ unsigned g_done;   // zero-init; last gemm2 block resets it each run

// ---------------- helpers ----------------
__device__ __forceinline__ float sigmoidf_(float x) { return 1.0f / (1.0f + __expf(-x)); }

__device__ __forceinline__ void mma8(float* c, const uint32_t* a, const uint32_t* b) {
    asm volatile(
        "mma.sync.aligned.m16n8k8.row.col.f32.tf32.tf32.f32 "
        "{%0,%1,%2,%3}, {%4,%5,%6,%7}, {%8,%9}, {%0,%1,%2,%3};\n"
        : "+f"(c[0]), "+f"(c[1]), "+f"(c[2]), "+f"(c[3])
        : "r"(a[0]), "r"(a[1]), "r"(a[2]), "r"(a[3]), "r"(b[0]), "r"(b[1]));
}

__device__ __forceinline__ void cpa16(uint32_t s, const void* g) {
    asm volatile("cp.async.cg.shared.global [%0], [%1], 16;\n" :: "r"(s), "l"(g));
}
__device__ __forceinline__ void cpa_commit() { asm volatile("cp.async.commit_group;\n"); }
__device__ __forceinline__ void cpa_wait1() { asm volatile("cp.async.wait_group 1;\n"); }
__device__ __forceinline__ void cpa_wait0() { asm volatile("cp.async.wait_group 0;\n"); }

// ---- swizzled float-offsets (R5-proven, BK=32 tiles) ----
// A tile: 128 rows x 32 cols. chunk' = (chunk + (r&7)) & 7
__device__ __forceinline__ int a_off(int r, int c) {
    return r * 32 + ((((c >> 2) + (r & 7)) & 7) << 2) + (c & 3);
}
// B tile: 32 rows x 64 cols. chunk' = (chunk + 2*(r&3)) & 15
__device__ __forceinline__ int b_off(int r, int c) {
    return r * 64 + ((((c >> 2) + 2 * (r & 3)) & 15) << 2) + (c & 3);
}

#define A_BUF 4096            // 128*32 floats
#define B_BUF 2048            // 32*64 floats
#define GSMEM_BYTES ((2 * A_BUF + 2 * B_BUF) * 4)   // 49152 = 48 KB; zero static smem on top

// ====================================================================
// Kernel 1: grayscale + patchify + 32x32 DFT + gate + patch sums
// ====================================================================
__global__ __launch_bounds__(256) void k_fft(const float* __restrict__ x,
                                             const float* __restrict__ lf,
                                             const float* __restrict__ mf,
                                             const float* __restrict__ hf) {
    __shared__ float sP[32][33];
    __shared__ float sYre[32][33];
    __shared__ float sYim[32][33];
    __shared__ float twc[32], tws[32];
    __shared__ float rA[8], rB[8];

    const int p = blockIdx.x;
    const int tid = threadIdx.x;
    const int b = p >> 6;
    const int gy = (p >> 3) & 7;
    const int gx = p & 7;

    if (tid < 32) {
        float ang = (float)tid * (1.0f / 16.0f);
        twc[tid] = cospif(ang);
        tws[tid] = sinpif(ang);
    }

    const float* xb = x + (size_t)b * 3 * 65536;
    float ls = 0.f, ls2 = 0.f;
#pragma unroll
    for (int ii = 0; ii < 4; ii++) {
        int idx = tid + ii * 256;
        int i = idx >> 5, j = idx & 31;
        int off = (gy * 32 + i) * 256 + gx * 32 + j;
        float v = 0.299f * xb[off] + 0.587f * xb[65536 + off] + 0.114f * xb[131072 + off];
        sP[i][j] = v;
        g_pr[p * DD + idx] = v;
        ls += v;
        ls2 += v * v;
    }
#pragma unroll
    for (int o = 16; o; o >>= 1) {
        ls += __shfl_xor_sync(0xffffffffu, ls, o);
        ls2 += __shfl_xor_sync(0xffffffffu, ls2, o);
    }
    if ((tid & 31) == 0) { rA[tid >> 5] = ls; rB[tid >> 5] = ls2; }
    __syncthreads();
    if (tid == 0) {
        float a = 0.f, c2 = 0.f;
#pragma unroll
        for (int q = 0; q < 8; q++) { a += rA[q]; c2 += rB[q]; }
        g_psum[p] = a;
        g_psumsq[p] = c2;
    }

#pragma unroll
    for (int ii = 0; ii < 4; ii++) {
        int idx = tid + ii * 256;
        int r = idx >> 5, k = idx & 31;
        float sre = 0.f, sim = 0.f;
        int t = 0;
#pragma unroll
        for (int c = 0; c < 32; c++) {
            float v = sP[r][c];
            sre = fmaf(v, twc[t], sre);
            sim = fmaf(-v, tws[t], sim);
            t = (t + k) & 31;
        }
        sYre[r][k] = sre;
        sYim[r][k] = sim;
    }
    __syncthreads();

    const float sl = sigmoidf_(lf[0]);
    const float sm = sigmoidf_(mf[0]);
    const float sh = sigmoidf_(hf[0]);

#pragma unroll
    for (int ii = 0; ii < 4; ii++) {
        int idx = tid + ii * 256;
        int j = idx >> 5, k = idx & 31;
        float fre = 0.f, fim = 0.f;
        int t = 0;
#pragma unroll
        for (int r = 0; r < 32; r++) {
            float cc = twc[t], ss = tws[t];
            float yre = sYre[r][k], yim = sYim[r][k];
            fre = fmaf(yre, cc, fre);
            fre = fmaf(yim, ss, fre);
            fim = fmaf(yim, cc, fim);
            fim = fmaf(-yre, ss, fim);
            t = (t + j) & 31;
        }
        float mag = sqrtf(fre * fre + fim * fim) * 0.03125f;
        float dy = (float)j - 15.5f, dx = (float)k - 15.5f;
        float r2 = dy * dy + dx * dx;
        float gate = (r2 <= 53.388889f) ? sl : ((r2 <= 213.555556f) ? sm : sh);
        g_mag[p * DD + idx] = mag * gate;
    }
}

// ====================================================================
// GEMM (R5-proven): BM=128, BN=64, BK=32; 256 threads = 8 warps (4m x 2n),
// 2-stage cp.async double buffer, swizzled 48 KB smem.
// ====================================================================

// Kernel 2: hidden = relu(mag @ W1 + b1)   M=1024 N=1536 K=1024
__global__ __launch_bounds__(256) void k_gemm1(const float* __restrict__ W1,
                                               const float* __restrict__ b1) {
    extern __shared__ float smem[];
    float* As = smem;                 // [2][A_BUF]
    float* Bs = smem + 2 * A_BUF;     // [2][B_BUF]

    const int tid = threadIdx.x;
    const int m0 = blockIdx.x * 128, n0 = blockIdx.y * 64;
    const int warp = tid >> 5, lane = tid & 31;
    const int wm = warp & 3, wn = warp >> 2;
    const int g = lane >> 2, tg = lane & 3;

    float acc[2][4][4];
#pragma unroll
    for (int i = 0; i < 2; i++)
#pragma unroll
        for (int j = 0; j < 4; j++)
#pragma unroll
            for (int e = 0; e < 4; e++) acc[i][j][e] = 0.f;

    const int arow = tid >> 3, acol = (tid & 7) << 2;
    const int brow = tid >> 4, bcol = (tid & 15) << 2;
    const uint32_t sA0 = (uint32_t)__cvta_generic_to_shared(As);
    const uint32_t sB0 = (uint32_t)__cvta_generic_to_shared(Bs);

    {
#pragma unroll
        for (int i = 0; i < 4; i++)
            cpa16(sA0 + a_off(arow + i * 32, acol) * 4,
                  &g_mag[(m0 + arow + i * 32) * 1024 + acol]);
#pragma unroll
        for (int i = 0; i < 2; i++)
            cpa16(sB0 + b_off(brow + i * 16, bcol) * 4,
                  &W1[(brow + i * 16) * 1536 + n0 + bcol]);
        cpa_commit();
    }

    for (int kt = 0; kt < 32; kt++) {
        const int cur = kt & 1;
        if (kt < 31) {
            const int k0 = (kt + 1) * 32;
            const int nb = cur ^ 1;
#pragma unroll
            for (int i = 0; i < 4; i++)
                cpa16(sA0 + (nb * A_BUF + a_off(arow + i * 32, acol)) * 4,
                      &g_mag[(m0 + arow + i * 32) * 1024 + k0 + acol]);
#pragma unroll
            for (int i = 0; i < 2; i++)
                cpa16(sB0 + (nb * B_BUF + b_off(brow + i * 16, bcol)) * 4,
                      &W1[(k0 + brow + i * 16) * 1536 + n0 + bcol]);
            cpa_commit();
            cpa_wait1();
        } else {
            cpa_wait0();
        }
        __syncthreads();

        const float* Ac = As + cur * A_BUF;
        const float* Bc = Bs + cur * B_BUF;
#pragma unroll
        for (int ks = 0; ks < 4; ks++) {
            uint32_t afr[2][4], bfr[4][2];
#pragma unroll
            for (int mt = 0; mt < 2; mt++) {
                int mr = wm * 32 + mt * 16 + g;
                int kk = ks * 8 + tg;
                afr[mt][0] = __float_as_uint(Ac[a_off(mr, kk)]);
                afr[mt][1] = __float_as_uint(Ac[a_off(mr + 8, kk)]);
                afr[mt][2] = __float_as_uint(Ac[a_off(mr, kk + 4)]);
                afr[mt][3] = __float_as_uint(Ac[a_off(mr + 8, kk + 4)]);
            }
#pragma unroll
            for (int nt = 0; nt < 4; nt++) {
                int nc = wn * 32 + nt * 8 + g;
                bfr[nt][0] = __float_as_uint(Bc[b_off(ks * 8 + tg, nc)]);
                bfr[nt][1] = __float_as_uint(Bc[b_off(ks * 8 + tg + 4, nc)]);
            }
#pragma unroll
            for (int mt = 0; mt < 2; mt++)
#pragma unroll
                for (int nt = 0; nt < 4; nt++) mma8(acc[mt][nt], afr[mt], bfr[nt]);
        }
        __syncthreads();
    }

#pragma unroll
    for (int mt = 0; mt < 2; mt++) {
        int row0 = m0 + wm * 32 + mt * 16 + g;
#pragma unroll
        for (int nt = 0; nt < 4; nt++) {
            int col = n0 + wn * 32 + nt * 8 + tg * 2;
            float bb0 = b1[col], bb1 = b1[col + 1];
            float2 o;
            o.x = fmaxf(acc[mt][nt][0] + bb0, 0.f);
            o.y = fmaxf(acc[mt][nt][1] + bb1, 0.f);
            *reinterpret_cast<float2*>(&g_hidden[row0 * 1536 + col]) = o;
            o.x = fmaxf(acc[mt][nt][2] + bb0, 0.f);
            o.y = fmaxf(acc[mt][nt][3] + bb1, 0.f);
            *reinterpret_cast<float2*>(&g_hidden[(row0 + 8) * 1536 + col]) = o;
        }
    }
}

// Kernel 3: attn = sigmoid(hidden @ W2 + b2); rowsum(mag*attn) -> g_wpart;
// last block (ticket) computes per-patch w + global stats. Zero static smem.
__global__ __launch_bounds__(256) void k_gemm2(const float* __restrict__ W2,
                                               const float* __restrict__ b2) {
    extern __shared__ float smem[];
    float* As = smem;
    float* Bs = smem + 2 * A_BUF;

    const int tid = threadIdx.x;
    const int m0 = blockIdx.x * 128, n0 = blockIdx.y * 64;
    const int warp = tid >> 5, lane = tid & 31;
    const int wm = warp & 3, wn = warp >> 2;
    const int g = lane >> 2, tg = lane & 3;

    float acc[2][4][4];
#pragma unroll
    for (int i = 0; i < 2; i++)
#pragma unroll
        for (int j = 0; j < 4; j++)
#pragma unroll
            for (int e = 0; e < 4; e++) acc[i][j][e] = 0.f;

    const int arow = tid >> 3, acol = (tid & 7) << 2;
    const int brow = tid >> 4, bcol = (tid & 15) << 2;
    const uint32_t sA0 = (uint32_t)__cvta_generic_to_shared(As);
    const uint32_t sB0 = (uint32_t)__cvta_generic_to_shared(Bs);

    {
#pragma unroll
        for (int i = 0; i < 4; i++)
            cpa16(sA0 + a_off(arow + i * 32, acol) * 4,
                  &g_hidden[(m0 + arow + i * 32) * 1536 + acol]);
#pragma unroll
        for (int i = 0; i < 2; i++)
            cpa16(sB0 + b_off(brow + i * 16, bcol) * 4,
                  &W2[(brow + i * 16) * 1024 + n0 + bcol]);
        cpa_commit();
    }

    for (int kt = 0; kt < 48; kt++) {
        const int cur = kt & 1;
        if (kt < 47) {
            const int k0 = (kt + 1) * 32;
            const int nb = cur ^ 1;
#pragma unroll
            for (int i = 0; i < 4; i++)
                cpa16(sA0 + (nb * A_BUF + a_off(arow + i * 32, acol)) * 4,
                      &g_hidden[(m0 + arow + i * 32) * 1536 + k0 + acol]);
#pragma unroll
            for (int i = 0; i < 2; i++)
                cpa16(sB0 + (nb * B_BUF + b_off(brow + i * 16, bcol)) * 4,
                      &W2[(k0 + brow + i * 16) * 1024 + n0 + bcol]);
            cpa_commit();
            cpa_wait1();
        } else {
            cpa_wait0();
        }
        __syncthreads();

        const float* Ac = As + cur * A_BUF;
        const float* Bc = Bs + cur * B_BUF;
#pragma unroll
        for (int ks = 0; ks < 4; ks++) {
            uint32_t afr[2][4], bfr[4][2];
#pragma unroll
            for (int mt = 0; mt < 2; mt++) {
                int mr = wm * 32 + mt * 16 + g;
                int kk = ks * 8 + tg;
                afr[mt][0] = __float_as_uint(Ac[a_off(mr, kk)]);
                afr[mt][1] = __float_as_uint(Ac[a_off(mr + 8, kk)]);
                afr[mt][2] = __float_as_uint(Ac[a_off(mr, kk + 4)]);
                afr[mt][3] = __float_as_uint(Ac[a_off(mr + 8, kk + 4)]);
            }
#pragma unroll
            for (int nt = 0; nt < 4; nt++) {
                int nc = wn * 32 + nt * 8 + g;
                bfr[nt][0] = __float_as_uint(Bc[b_off(ks * 8 + tg, nc)]);
                bfr[nt][1] = __float_as_uint(Bc[b_off(ks * 8 + tg + 4, nc)]);
            }
#pragma unroll
            for (int mt = 0; mt < 2; mt++)
#pragma unroll
                for (int nt = 0; nt < 4; nt++) mma8(acc[mt][nt], afr[mt], bfr[nt]);
        }
        __syncthreads();
    }

    // smem overlays (dynamic region; mainloop done, contents dead):
    float*    sRow  = smem;                               // [0,256): 128 rows x 2
    unsigned* sRank = reinterpret_cast<unsigned*>(smem + 256);
    float*    s_ra  = smem + 272;
    float*    s_rb  = smem + 280;

    // epilogue: sigmoid, multiply by mag, per-row partial sums
    float rs[2][2] = {{0.f, 0.f}, {0.f, 0.f}};
#pragma unroll
    for (int mt = 0; mt < 2; mt++) {
        int row0 = m0 + wm * 32 + mt * 16 + g;
#pragma unroll
        for (int nt = 0; nt < 4; nt++) {
            int col = n0 + wn * 32 + nt * 8 + tg * 2;
            float bb0 = b2[col], bb1 = b2[col + 1];
            rs[mt][0] += g_mag[row0 * 1024 + col]           * sigmoidf_(acc[mt][nt][0] + bb0);
            rs[mt][0] += g_mag[row0 * 1024 + col + 1]       * sigmoidf_(acc[mt][nt][1] + bb1);
            rs[mt][1] += g_mag[(row0 + 8) * 1024 + col]     * sigmoidf_(acc[mt][nt][2] + bb0);
            rs[mt][1] += g_mag[(row0 + 8) * 1024 + col + 1] * sigmoidf_(acc[mt][nt][3] + bb1);
        }
    }
#pragma unroll
    for (int mt = 0; mt < 2; mt++)
#pragma unroll
        for (int hh = 0; hh < 2; hh++) {
            float v = rs[mt][hh];
            v += __shfl_xor_sync(0xffffffffu, v, 1);
            v += __shfl_xor_sync(0xffffffffu, v, 2);
            if (tg == 0) sRow[(wm * 32 + mt * 16 + hh * 8 + g) * 2 + wn] = v;
        }
    __syncthreads();
    if (tid < 128) g_wpart[(m0 + tid) * 16 + blockIdx.y] = sRow[tid * 2] + sRow[tid * 2 + 1];

    // ---- last-block stats: write -> fence -> barrier -> ticket -> barrier ----
    __threadfence();
    __syncthreads();
    if (tid == 0) sRank[0] = atomicAdd(&g_done, 1u);
    __syncthreads();
    if (sRank[0] == 127u) {        // grid is (8,16) = 128 blocks
        if (tid == 0) g_done = 0u; // reset for next graph replay
        float va = 0.f, vb = 0.f;
#pragma unroll
        for (int q = 0; q < 4; q++) {
            int p = tid + q * 256;
            const float4* w4 = reinterpret_cast<const float4*>(&g_wpart[p * 16]);
            float4 a0 = w4[0], a1 = w4[1], a2 = w4[2], a3 = w4[3];
            float s = (a0.x + a0.y + a0.z + a0.w) + (a1.x + a1.y + a1.z + a1.w)
                    + (a2.x + a2.y + a2.z + a2.w) + (a3.x + a3.y + a3.z + a3.w);
            float wf = 1.0f + s * (1.0f / 1024.0f);
            g_wf[p] = wf;
            va += wf * g_psum[p];
            vb += wf * wf * g_psumsq[p];
        }
#pragma unroll
        for (int o = 16; o; o >>= 1) {
            va += __shfl_xor_sync(0xffffffffu, va, o);
            vb += __shfl_xor_sync(0xffffffffu, vb, o);
        }
        if (lane == 0) { s_ra[warp] = va; s_rb[warp] = vb; }
        __syncthreads();
        if (tid == 0) {
            float xa = 0.f, xb = 0.f;
#pragma unroll
            for (int q = 0; q < 8; q++) { xa += s_ra[q]; xb += s_rb[q]; }
            float mu = xa * (1.0f / 1048576.0f);
            float ex2 = xb * (1.0f / 1048576.0f);
            g_stats[0] = mu;
            g_stats[1] = ex2 - mu * mu;
        }
    }
}

// ====================================================================
// Kernel 4: out = relu(s_c*x_rec + o_c) — write-bound, streaming stores
// ====================================================================
__global__ __launch_bounds__(256) void k_final(const float* __restrict__ wproj,
                                               const float* __restrict__ gamma,
                                               const float* __restrict__ beta,
                                               float* __restrict__ out) {
    __shared__ float sS[64], sO[64];
    const int tid = threadIdx.x;
    if (tid < 64) {
        float mu = g_stats[0], var = g_stats[1];
        float wp = wproj[tid];
        float sc = gamma[tid] * wp * rsqrtf(fmaf(wp * wp, var, 1e-5f));
        sS[tid] = sc;
        sO[tid] = beta[tid] - sc * mu;
    }
    __syncthreads();

    const int t = blockIdx.x * 256 + tid;
    const int b = t >> 14;
    const int rem = t & 16383;
    const int h = rem >> 6;
    const int w4 = rem & 63;
    const int p = b * 64 + (h >> 5) * 8 + (w4 >> 3);

    float4 xr = *reinterpret_cast<const float4*>(&g_pr[p * DD + (h & 31) * 32 + (w4 & 7) * 4]);
    const float wf = g_wf[p];
    xr.x *= wf; xr.y *= wf; xr.z *= wf; xr.w *= wf;

    float* ob = out + ((size_t)b << 22) + (h << 8) + (w4 << 2);
#pragma unroll 8
    for (int ch = 0; ch < 64; ch++) {
        float s = sS[ch], o = sO[ch];
        float4 v;
        v.x = fmaxf(fmaf(s, xr.x, o), 0.f);
        v.y = fmaxf(fmaf(s, xr.y, o), 0.f);
        v.z = fmaxf(fmaf(s, xr.z, o), 0.f);
        v.w = fmaxf(fmaf(s, xr.w, o), 0.f);
        __stcs(reinterpret_cast<float4*>(ob + ((size_t)ch << 16)), v);
    }
}

// ====================================================================
extern "C" void kernel_launch(void* const* d_in, const int* in_sizes, int n_in,
                              void* d_out, int out_size) {
    (void)in_sizes; (void)n_in; (void)out_size;
    const float* x     = (const float*)d_in[0];
    const float* W1    = (const float*)d_in[1];
    const float* b1    = (const float*)d_in[2];
    const float* W2    = (const float*)d_in[3];
    const float* b2    = (const float*)d_in[4];
    const float* wproj = (const float*)d_in[5];
    const float* gamma = (const float*)d_in[6];
    const float* beta  = (const float*)d_in[7];
    const float* lf    = (const float*)d_in[8];
    const float* mf    = (const float*)d_in[9];
    const float* hf    = (const float*)d_in[10];
    float* out = (float*)d_out;

    k_fft<<<1024, 256>>>(x, lf, mf, hf);
    k_gemm1<<<dim3(8, 24), 256, GSMEM_BYTES>>>(W1, b1);
    k_gemm2<<<dim3(8, 16), 256, GSMEM_BYTES>>>(W2, b2);
    k_final<<<1024, 256>>>(wproj, gamma, beta, out);
}

// round 10
// speedup vs baseline: 1.4482x; 1.4482x over previous
#include <cuda_runtime.h>
#include <cstdint>

// ---------------- problem constants ----------------
#define NP   1024
#define DD   1024
#define HID  1536

// ---------------- scratch (device globals; no allocations) ----------------
__device__ float g_pr[NP * DD];
__device__ float g_mag[NP * DD];
__device__ float g_hidden[NP * HID];
__device__ float g_wpart[NP * 16];
__device__ float g_wf[NP];
__device__ float g_psum[NP];
__device__ float g_psumsq[NP];
__device__ float g_stats[2];
__device__ unsigned g_done;   // zero-init; last gemm2 block resets it each run

// ---------------- helpers ----------------
__device__ __forceinline__ float sigmoidf_(float x) { return 1.0f / (1.0f + __expf(-x)); }

__device__ __forceinline__ void mma8(float* c, const uint32_t* a, const uint32_t* b) {
    asm volatile(
        "mma.sync.aligned.m16n8k8.row.col.f32.tf32.tf32.f32 "
        "{%0,%1,%2,%3}, {%4,%5,%6,%7}, {%8,%9}, {%0,%1,%2,%3};\n"
        : "+f"(c[0]), "+f"(c[1]), "+f"(c[2]), "+f"(c[3])
        : "r"(a[0]), "r"(a[1]), "r"(a[2]), "r"(a[3]), "r"(b[0]), "r"(b[1]));
}

__device__ __forceinline__ void cpa16(uint32_t s, const void* g) {
    asm volatile("cp.async.cg.shared.global [%0], [%1], 16;\n" :: "r"(s), "l"(g));
}
__device__ __forceinline__ void cpa_commit() { asm volatile("cp.async.commit_group;\n"); }
__device__ __forceinline__ void cpa_wait1() { asm volatile("cp.async.wait_group 1;\n"); }
__device__ __forceinline__ void cpa_wait0() { asm volatile("cp.async.wait_group 0;\n"); }

// ---- swizzled float-offsets (R5-proven, BK=32 tiles) ----
// A tile: 128 rows x 32 cols. chunk' = (chunk + (r&7)) & 7
__device__ __forceinline__ int a_off(int r, int c) {
    return r * 32 + ((((c >> 2) + (r & 7)) & 7) << 2) + (c & 3);
}
// B tile: 32 rows x 64 cols. chunk' = (chunk + 2*(r&3)) & 15
__device__ __forceinline__ int b_off(int r, int c) {
    return r * 64 + ((((c >> 2) + 2 * (r & 3)) & 15) << 2) + (c & 3);
}

#define A_BUF 4096            // 128*32 floats
#define B_BUF 2048            // 32*64 floats
#define GSMEM_BYTES ((2 * A_BUF + 2 * B_BUF) * 4)   // 49152 = 48 KB; zero static smem on top

// ====================================================================
// Kernel 1: grayscale + patchify + 32x32 DFT + gate + patch sums
// ====================================================================
__global__ __launch_bounds__(256) void k_fft(const float* __restrict__ x,
                                             const float* __restrict__ lf,
                                             const float* __restrict__ mf,
                                             const float* __restrict__ hf) {
    __shared__ float sP[32][33];
    __shared__ float sYre[32][33];
    __shared__ float sYim[32][33];
    __shared__ float twc[32], tws[32];
    __shared__ float rA[8], rB[8];

    const int p = blockIdx.x;
    const int tid = threadIdx.x;
    const int b = p >> 6;
    const int gy = (p >> 3) & 7;
    const int gx = p & 7;

    if (tid < 32) {
        float ang = (float)tid * (1.0f / 16.0f);
        twc[tid] = cospif(ang);
        tws[tid] = sinpif(ang);
    }

    const float* xb = x + (size_t)b * 3 * 65536;
    float ls = 0.f, ls2 = 0.f;
#pragma unroll
    for (int ii = 0; ii < 4; ii++) {
        int idx = tid + ii * 256;
        int i = idx >> 5, j = idx & 31;
        int off = (gy * 32 + i) * 256 + gx * 32 + j;
        float v = 0.299f * xb[off] + 0.587f * xb[65536 + off] + 0.114f * xb[131072 + off];
        sP[i][j] = v;
        g_pr[p * DD + idx] = v;
        ls += v;
        ls2 += v * v;
    }
#pragma unroll
    for (int o = 16; o; o >>= 1) {
        ls += __shfl_xor_sync(0xffffffffu, ls, o);
        ls2 += __shfl_xor_sync(0xffffffffu, ls2, o);
    }
    if ((tid & 31) == 0) { rA[tid >> 5] = ls; rB[tid >> 5] = ls2; }
    __syncthreads();
    if (tid == 0) {
        float a = 0.f, c2 = 0.f;
#pragma unroll
        for (int q = 0; q < 8; q++) { a += rA[q]; c2 += rB[q]; }
        g_psum[p] = a;
        g_psumsq[p] = c2;
    }

#pragma unroll
    for (int ii = 0; ii < 4; ii++) {
        int idx = tid + ii * 256;
        int r = idx >> 5, k = idx & 31;
        float sre = 0.f, sim = 0.f;
        int t = 0;
#pragma unroll
        for (int c = 0; c < 32; c++) {
            float v = sP[r][c];
            sre = fmaf(v, twc[t], sre);
            sim = fmaf(-v, tws[t], sim);
            t = (t + k) & 31;
        }
        sYre[r][k] = sre;
        sYim[r][k] = sim;
    }
    __syncthreads();

    const float sl = sigmoidf_(lf[0]);
    const float sm = sigmoidf_(mf[0]);
    const float sh = sigmoidf_(hf[0]);

#pragma unroll
    for (int ii = 0; ii < 4; ii++) {
        int idx = tid + ii * 256;
        int j = idx >> 5, k = idx & 31;
        float fre = 0.f, fim = 0.f;
        int t = 0;
#pragma unroll
        for (int r = 0; r < 32; r++) {
            float cc = twc[t], ss = tws[t];
            float yre = sYre[r][k], yim = sYim[r][k];
            fre = fmaf(yre, cc, fre);
            fre = fmaf(yim, ss, fre);
            fim = fmaf(yim, cc, fim);
            fim = fmaf(-yre, ss, fim);
            t = (t + j) & 31;
        }
        float mag = sqrtf(fre * fre + fim * fim) * 0.03125f;
        float dy = (float)j - 15.5f, dx = (float)k - 15.5f;
        float r2 = dy * dy + dx * dx;
        float gate = (r2 <= 53.388889f) ? sl : ((r2 <= 213.555556f) ? sm : sh);
        g_mag[p * DD + idx] = mag * gate;
    }
}

// ====================================================================
// GEMM (R5-proven): BM=128, BN=64, BK=32; 256 threads = 8 warps (4m x 2n),
// 2-stage cp.async double buffer, swizzled 48 KB smem.
// ====================================================================

// Kernel 2: hidden = relu(mag @ W1 + b1)   M=1024 N=1536 K=1024
__global__ __launch_bounds__(256) void k_gemm1(const float* __restrict__ W1,
                                               const float* __restrict__ b1) {
    extern __shared__ float smem[];
    float* As = smem;                 // [2][A_BUF]
    float* Bs = smem + 2 * A_BUF;     // [2][B_BUF]

    const int tid = threadIdx.x;
    const int m0 = blockIdx.x * 128, n0 = blockIdx.y * 64;
    const int warp = tid >> 5, lane = tid & 31;
    const int wm = warp & 3, wn = warp >> 2;
    const int g = lane >> 2, tg = lane & 3;

    float acc[2][4][4];
#pragma unroll
    for (int i = 0; i < 2; i++)
#pragma unroll
        for (int j = 0; j < 4; j++)
#pragma unroll
            for (int e = 0; e < 4; e++) acc[i][j][e] = 0.f;

    const int arow = tid >> 3, acol = (tid & 7) << 2;
    const int brow = tid >> 4, bcol = (tid & 15) << 2;
    const uint32_t sA0 = (uint32_t)__cvta_generic_to_shared(As);
    const uint32_t sB0 = (uint32_t)__cvta_generic_to_shared(Bs);

    {
#pragma unroll
        for (int i = 0; i < 4; i++)
            cpa16(sA0 + a_off(arow + i * 32, acol) * 4,
                  &g_mag[(m0 + arow + i * 32) * 1024 + acol]);
#pragma unroll
        for (int i = 0; i < 2; i++)
            cpa16(sB0 + b_off(brow + i * 16, bcol) * 4,
                  &W1[(brow + i * 16) * 1536 + n0 + bcol]);
        cpa_commit();
    }

    for (int kt = 0; kt < 32; kt++) {
        const int cur = kt & 1;
        if (kt < 31) {
            const int k0 = (kt + 1) * 32;
            const int nb = cur ^ 1;
#pragma unroll
            for (int i = 0; i < 4; i++)
                cpa16(sA0 + (nb * A_BUF + a_off(arow + i * 32, acol)) * 4,
                      &g_mag[(m0 + arow + i * 32) * 1024 + k0 + acol]);
#pragma unroll
            for (int i = 0; i < 2; i++)
                cpa16(sB0 + (nb * B_BUF + b_off(brow + i * 16, bcol)) * 4,
                      &W1[(k0 + brow + i * 16) * 1536 + n0 + bcol]);
            cpa_commit();
            cpa_wait1();
        } else {
            cpa_wait0();
        }
        __syncthreads();

        const float* Ac = As + cur * A_BUF;
        const float* Bc = Bs + cur * B_BUF;
#pragma unroll
        for (int ks = 0; ks < 4; ks++) {
            uint32_t afr[2][4], bfr[4][2];
#pragma unroll
            for (int mt = 0; mt < 2; mt++) {
                int mr = wm * 32 + mt * 16 + g;
                int kk = ks * 8 + tg;
                afr[mt][0] = __float_as_uint(Ac[a_off(mr, kk)]);
                afr[mt][1] = __float_as_uint(Ac[a_off(mr + 8, kk)]);
                afr[mt][2] = __float_as_uint(Ac[a_off(mr, kk + 4)]);
                afr[mt][3] = __float_as_uint(Ac[a_off(mr + 8, kk + 4)]);
            }
#pragma unroll
            for (int nt = 0; nt < 4; nt++) {
                int nc = wn * 32 + nt * 8 + g;
                bfr[nt][0] = __float_as_uint(Bc[b_off(ks * 8 + tg, nc)]);
                bfr[nt][1] = __float_as_uint(Bc[b_off(ks * 8 + tg + 4, nc)]);
            }
#pragma unroll
            for (int mt = 0; mt < 2; mt++)
#pragma unroll
                for (int nt = 0; nt < 4; nt++) mma8(acc[mt][nt], afr[mt], bfr[nt]);
        }
        __syncthreads();
    }

#pragma unroll
    for (int mt = 0; mt < 2; mt++) {
        int row0 = m0 + wm * 32 + mt * 16 + g;
#pragma unroll
        for (int nt = 0; nt < 4; nt++) {
            int col = n0 + wn * 32 + nt * 8 + tg * 2;
            float bb0 = b1[col], bb1 = b1[col + 1];
            float2 o;
            o.x = fmaxf(acc[mt][nt][0] + bb0, 0.f);
            o.y = fmaxf(acc[mt][nt][1] + bb1, 0.f);
            *reinterpret_cast<float2*>(&g_hidden[row0 * 1536 + col]) = o;
            o.x = fmaxf(acc[mt][nt][2] + bb0, 0.f);
            o.y = fmaxf(acc[mt][nt][3] + bb1, 0.f);
            *reinterpret_cast<float2*>(&g_hidden[(row0 + 8) * 1536 + col]) = o;
        }
    }
}

// Kernel 3: attn = sigmoid(hidden @ W2 + b2); rowsum(mag*attn) -> g_wpart;
// last block (ticket) computes per-patch w + global stats. Zero static smem.
__global__ __launch_bounds__(256) void k_gemm2(const float* __restrict__ W2,
                                               const float* __restrict__ b2) {
    extern __shared__ float smem[];
    float* As = smem;
    float* Bs = smem + 2 * A_BUF;

    const int tid = threadIdx.x;
    const int m0 = blockIdx.x * 128, n0 = blockIdx.y * 64;
    const int warp = tid >> 5, lane = tid & 31;
    const int wm = warp & 3, wn = warp >> 2;
    const int g = lane >> 2, tg = lane & 3;

    float acc[2][4][4];
#pragma unroll
    for (int i = 0; i < 2; i++)
#pragma unroll
        for (int j = 0; j < 4; j++)
#pragma unroll
            for (int e = 0; e < 4; e++) acc[i][j][e] = 0.f;

    const int arow = tid >> 3, acol = (tid & 7) << 2;
    const int brow = tid >> 4, bcol = (tid & 15) << 2;
    const uint32_t sA0 = (uint32_t)__cvta_generic_to_shared(As);
    const uint32_t sB0 = (uint32_t)__cvta_generic_to_shared(Bs);

    {
#pragma unroll
        for (int i = 0; i < 4; i++)
            cpa16(sA0 + a_off(arow + i * 32, acol) * 4,
                  &g_hidden[(m0 + arow + i * 32) * 1536 + acol]);
#pragma unroll
        for (int i = 0; i < 2; i++)
            cpa16(sB0 + b_off(brow + i * 16, bcol) * 4,
                  &W2[(brow + i * 16) * 1024 + n0 + bcol]);
        cpa_commit();
    }

    for (int kt = 0; kt < 48; kt++) {
        const int cur = kt & 1;
        if (kt < 47) {
            const int k0 = (kt + 1) * 32;
            const int nb = cur ^ 1;
#pragma unroll
            for (int i = 0; i < 4; i++)
                cpa16(sA0 + (nb * A_BUF + a_off(arow + i * 32, acol)) * 4,
                      &g_hidden[(m0 + arow + i * 32) * 1536 + k0 + acol]);
#pragma unroll
            for (int i = 0; i < 2; i++)
                cpa16(sB0 + (nb * B_BUF + b_off(brow + i * 16, bcol)) * 4,
                      &W2[(k0 + brow + i * 16) * 1024 + n0 + bcol]);
            cpa_commit();
            cpa_wait1();
        } else {
            cpa_wait0();
        }
        __syncthreads();

        const float* Ac = As + cur * A_BUF;
        const float* Bc = Bs + cur * B_BUF;
#pragma unroll
        for (int ks = 0; ks < 4; ks++) {
            uint32_t afr[2][4], bfr[4][2];
#pragma unroll
            for (int mt = 0; mt < 2; mt++) {
                int mr = wm * 32 + mt * 16 + g;
                int kk = ks * 8 + tg;
                afr[mt][0] = __float_as_uint(Ac[a_off(mr, kk)]);
                afr[mt][1] = __float_as_uint(Ac[a_off(mr + 8, kk)]);
                afr[mt][2] = __float_as_uint(Ac[a_off(mr, kk + 4)]);
                afr[mt][3] = __float_as_uint(Ac[a_off(mr + 8, kk + 4)]);
            }
#pragma unroll
            for (int nt = 0; nt < 4; nt++) {
                int nc = wn * 32 + nt * 8 + g;
                bfr[nt][0] = __float_as_uint(Bc[b_off(ks * 8 + tg, nc)]);
                bfr[nt][1] = __float_as_uint(Bc[b_off(ks * 8 + tg + 4, nc)]);
            }
#pragma unroll
            for (int mt = 0; mt < 2; mt++)
#pragma unroll
                for (int nt = 0; nt < 4; nt++) mma8(acc[mt][nt], afr[mt], bfr[nt]);
        }
        __syncthreads();
    }

    // smem overlays (dynamic region; mainloop done, contents dead):
    float*    sRow  = smem;                               // [0,256): 128 rows x 2
    unsigned* sRank = reinterpret_cast<unsigned*>(smem + 256);
    float*    s_ra  = smem + 272;
    float*    s_rb  = smem + 280;

    // epilogue: sigmoid, multiply by mag, per-row partial sums
    float rs[2][2] = {{0.f, 0.f}, {0.f, 0.f}};
#pragma unroll
    for (int mt = 0; mt < 2; mt++) {
        int row0 = m0 + wm * 32 + mt * 16 + g;
#pragma unroll
        for (int nt = 0; nt < 4; nt++) {
            int col = n0 + wn * 32 + nt * 8 + tg * 2;
            float bb0 = b2[col], bb1 = b2[col + 1];
            rs[mt][0] += g_mag[row0 * 1024 + col]           * sigmoidf_(acc[mt][nt][0] + bb0);
            rs[mt][0] += g_mag[row0 * 1024 + col + 1]       * sigmoidf_(acc[mt][nt][1] + bb1);
            rs[mt][1] += g_mag[(row0 + 8) * 1024 + col]     * sigmoidf_(acc[mt][nt][2] + bb0);
            rs[mt][1] += g_mag[(row0 + 8) * 1024 + col + 1] * sigmoidf_(acc[mt][nt][3] + bb1);
        }
    }
#pragma unroll
    for (int mt = 0; mt < 2; mt++)
#pragma unroll
        for (int hh = 0; hh < 2; hh++) {
            float v = rs[mt][hh];
            v += __shfl_xor_sync(0xffffffffu, v, 1);
            v += __shfl_xor_sync(0xffffffffu, v, 2);
            if (tg == 0) sRow[(wm * 32 + mt * 16 + hh * 8 + g) * 2 + wn] = v;
        }
    __syncthreads();
    if (tid < 128) g_wpart[(m0 + tid) * 16 + blockIdx.y] = sRow[tid * 2] + sRow[tid * 2 + 1];

    // ---- last-block stats: write -> fence -> barrier -> ticket -> barrier ----
    __threadfence();
    __syncthreads();
    if (tid == 0) sRank[0] = atomicAdd(&g_done, 1u);
    __syncthreads();
    if (sRank[0] == 127u) {        // grid is (8,16) = 128 blocks
        if (tid == 0) g_done = 0u; // reset for next graph replay
        float va = 0.f, vb = 0.f;
#pragma unroll
        for (int q = 0; q < 4; q++) {
            int p = tid + q * 256;
            const float4* w4 = reinterpret_cast<const float4*>(&g_wpart[p * 16]);
            float4 a0 = w4[0], a1 = w4[1], a2 = w4[2], a3 = w4[3];
            float s = (a0.x + a0.y + a0.z + a0.w) + (a1.x + a1.y + a1.z + a1.w)
                    + (a2.x + a2.y + a2.z + a2.w) + (a3.x + a3.y + a3.z + a3.w);
            float wf = 1.0f + s * (1.0f / 1024.0f);
            g_wf[p] = wf;
            va += wf * g_psum[p];
            vb += wf * wf * g_psumsq[p];
        }
#pragma unroll
        for (int o = 16; o; o >>= 1) {
            va += __shfl_xor_sync(0xffffffffu, va, o);
            vb += __shfl_xor_sync(0xffffffffu, vb, o);
        }
        if (lane == 0) { s_ra[warp] = va; s_rb[warp] = vb; }
        __syncthreads();
        if (tid == 0) {
            float xa = 0.f, xb = 0.f;
#pragma unroll
            for (int q = 0; q < 8; q++) { xa += s_ra[q]; xb += s_rb[q]; }
            float mu = xa * (1.0f / 1048576.0f);
            float ex2 = xb * (1.0f / 1048576.0f);
            g_stats[0] = mu;
            g_stats[1] = ex2 - mu * mu;
        }
    }
}

// ====================================================================
// Kernel 4: out = relu(s_c*x_rec + o_c) — write-bound, plain float4 stores
// (measured best: 43.3us @ 62% DRAM; __stcs regressed to 61.5us — reverted)
// ====================================================================
__global__ __launch_bounds__(256) void k_final(const float* __restrict__ wproj,
                                               const float* __restrict__ gamma,
                                               const float* __restrict__ beta,
                                               float* __restrict__ out) {
    __shared__ float sS[64], sO[64];
    const int tid = threadIdx.x;
    if (tid < 64) {
        float mu = g_stats[0], var = g_stats[1];
        float wp = wproj[tid];
        float sc = gamma[tid] * wp * rsqrtf(fmaf(wp * wp, var, 1e-5f));
        sS[tid] = sc;
        sO[tid] = beta[tid] - sc * mu;
    }
    __syncthreads();

    const int t = blockIdx.x * 256 + tid;
    const int b = t >> 14;
    const int rem = t & 16383;
    const int h = rem >> 6;
    const int w4 = rem & 63;
    const int p = b * 64 + (h >> 5) * 8 + (w4 >> 3);

    float4 xr = *reinterpret_cast<const float4*>(&g_pr[p * DD + (h & 31) * 32 + (w4 & 7) * 4]);
    const float wf = g_wf[p];
    xr.x *= wf; xr.y *= wf; xr.z *= wf; xr.w *= wf;

    float* ob = out + ((size_t)b << 22) + (h << 8) + (w4 << 2);
#pragma unroll 8
    for (int ch = 0; ch < 64; ch++) {
        float s = sS[ch], o = sO[ch];
        float4 v;
        v.x = fmaxf(fmaf(s, xr.x, o), 0.f);
        v.y = fmaxf(fmaf(s, xr.y, o), 0.f);
        v.z = fmaxf(fmaf(s, xr.z, o), 0.f);
        v.w = fmaxf(fmaf(s, xr.w, o), 0.f);
        *reinterpret_cast<float4*>(ob + ((size_t)ch << 16)) = v;
    }
}

// ====================================================================
extern "C" void kernel_launch(void* const* d_in, const int* in_sizes, int n_in,
                              void* d_out, int out_size) {
    (void)in_sizes; (void)n_in; (void)out_size;
    const float* x     = (const float*)d_in[0];
    const float* W1    = (const float*)d_in[1];
    const float* b1    = (const float*)d_in[2];
    const float* W2    = (const float*)d_in[3];
    const float* b2    = (const float*)d_in[4];
    const float* wproj = (const float*)d_in[5];
    const float* gamma = (const float*)d_in[6];
    const float* beta  = (const float*)d_in[7];
    const float* lf    = (const float*)d_in[8];
    const float* mf    = (const float*)d_in[9];
    const float* hf    = (const float*)d_in[10];
    float* out = (float*)d_out;

    k_fft<<<1024, 256>>>(x, lf, mf, hf);
    k_gemm1<<<dim3(8, 24), 256, GSMEM_BYTES>>>(W1, b1);
    k_gemm2<<<dim3(8, 16), 256, GSMEM_BYTES>>>(W2, b2);
    k_final<<<1024, 256>>>(wproj, gamma, beta, out);
}

// round 11
// speedup vs baseline: 1.7895x; 1.2356x over previous
#include <cuda_runtime.h>
#include <cuda_bf16.h>
#include <cstdint>

// ---------------- problem constants ----------------
#define NP   1024
#define DD   1024
#define HID  1536

// ---------------- scratch (device globals; no allocations) ----------------
__device__ float g_pr[NP * DD];
__device__ float g_mag[NP * DD];                 // fp32 mag (epilogue)
__device__ __nv_bfloat16 g_magh[NP * DD];        // bf16 mag (GEMM A)
__device__ __nv_bfloat16 g_hiddenh[NP * HID];    // bf16 hidden
__device__ __nv_bfloat16 g_w1t[HID * DD];        // W1^T bf16 [n=1536][k=1024]
__device__ __nv_bfloat16 g_w2t[DD * HID];        // W2^T bf16 [n=1024][k=1536]
__device__ float g_wpart[NP * 16];
__device__ float g_wf[NP];
__device__ float g_psum[NP];
__device__ float g_psumsq[NP];
__device__ float g_stats[2];
__device__ unsigned g_done;

// ---------------- helpers ----------------
__device__ __forceinline__ float sigmoidf_(float x) { return 1.0f / (1.0f + __expf(-x)); }

__device__ __forceinline__ void mma16(float* c, const uint32_t* a, const uint32_t* b) {
    asm volatile(
        "mma.sync.aligned.m16n8k16.row.col.f32.bf16.bf16.f32 "
        "{%0,%1,%2,%3}, {%4,%5,%6,%7}, {%8,%9}, {%0,%1,%2,%3};\n"
        : "+f"(c[0]), "+f"(c[1]), "+f"(c[2]), "+f"(c[3])
        : "r"(a[0]), "r"(a[1]), "r"(a[2]), "r"(a[3]), "r"(b[0]), "r"(b[1]));
}

__device__ __forceinline__ void cpa16(uint32_t s, const void* g) {
    asm volatile("cp.async.cg.shared.global [%0], [%1], 16;\n" :: "r"(s), "l"(g));
}
__device__ __forceinline__ void cpa_commit() { asm volatile("cp.async.commit_group;\n"); }
__device__ __forceinline__ void cpa_wait1() { asm volatile("cp.async.wait_group 1;\n"); }
__device__ __forceinline__ void cpa_wait0() { asm volatile("cp.async.wait_group 0;\n"); }

// bf16 tile addressing: rows of 128 bytes (64 bf16), 16B-chunk XOR swizzle.
// swz(r, byte): byte in [0,128), XOR rotates chunk bits [4:6] by (r&7).
__device__ __forceinline__ int swz(int r, int byte) {
    return r * 128 + (byte ^ ((r & 7) << 4));
}

// stage: A tile 128x64 bf16 = 16384 B at +0; B tile 64x64 bf16 = 8192 B at +16384
#define STAGE_B 24576
#define B_OFF   16384
#define GSMEM_BYTES (2 * STAGE_B)   // 49152 = 48 KB, zero static smem on top

// ====================================================================
// Kernel 0: weight prep — fp32 -> bf16 + transpose to [n][k]
// grid (48,48,2), block (32,8)
// ====================================================================
__global__ void k_prep(const float* __restrict__ W1, const float* __restrict__ W2) {
    __shared__ float t[32][33];
    const int z = blockIdx.z;
    const float* src = z ? W2 : W1;
    __nv_bfloat16* dst = z ? g_w2t : g_w1t;
    const int srows = z ? HID : DD;    // src k-dim
    const int scols = z ? DD : HID;    // src n-dim
    const int bx = blockIdx.x, by = blockIdx.y;
    if (bx * 32 >= scols || by * 32 >= srows) return;
    const int tx = threadIdx.x, ty = threadIdx.y;
#pragma unroll
    for (int j = 0; j < 4; j++) {
        int r = by * 32 + ty + j * 8;
        t[ty + j * 8][tx] = src[r * scols + bx * 32 + tx];
    }
    __syncthreads();
#pragma unroll
    for (int j = 0; j < 4; j++) {
        int drow = bx * 32 + ty + j * 8;   // n
        int dcol = by * 32 + tx;           // k
        dst[drow * srows + dcol] = __float2bfloat16_rn(t[tx][ty + j * 8]);
    }
}

// ====================================================================
// Kernel 1: grayscale + patchify + 32x32 DFT + gate + patch sums
// ====================================================================
__global__ __launch_bounds__(256) void k_fft(const float* __restrict__ x,
                                             const float* __restrict__ lf,
                                             const float* __restrict__ mf,
                                             const float* __restrict__ hf) {
    __shared__ float sP[32][33];
    __shared__ float sYre[32][33];
    __shared__ float sYim[32][33];
    __shared__ float twc[32], tws[32];
    __shared__ float rA[8], rB[8];

    const int p = blockIdx.x;
    const int tid = threadIdx.x;
    const int b = p >> 6;
    const int gy = (p >> 3) & 7;
    const int gx = p & 7;

    if (tid < 32) {
        float ang = (float)tid * (1.0f / 16.0f);
        twc[tid] = cospif(ang);
        tws[tid] = sinpif(ang);
    }

    const float* xb = x + (size_t)b * 3 * 65536;
    float ls = 0.f, ls2 = 0.f;
#pragma unroll
    for (int ii = 0; ii < 4; ii++) {
        int idx = tid + ii * 256;
        int i = idx >> 5, j = idx & 31;
        int off = (gy * 32 + i) * 256 + gx * 32 + j;
        float v = 0.299f * xb[off] + 0.587f * xb[65536 + off] + 0.114f * xb[131072 + off];
        sP[i][j] = v;
        g_pr[p * DD + idx] = v;
        ls += v;
        ls2 += v * v;
    }
#pragma unroll
    for (int o = 16; o; o >>= 1) {
        ls += __shfl_xor_sync(0xffffffffu, ls, o);
        ls2 += __shfl_xor_sync(0xffffffffu, ls2, o);
    }
    if ((tid & 31) == 0) { rA[tid >> 5] = ls; rB[tid >> 5] = ls2; }
    __syncthreads();
    if (tid == 0) {
        float a = 0.f, c2 = 0.f;
#pragma unroll
        for (int q = 0; q < 8; q++) { a += rA[q]; c2 += rB[q]; }
        g_psum[p] = a;
        g_psumsq[p] = c2;
    }

#pragma unroll
    for (int ii = 0; ii < 4; ii++) {
        int idx = tid + ii * 256;
        int r = idx >> 5, k = idx & 31;
        float sre = 0.f, sim = 0.f;
        int t = 0;
#pragma unroll
        for (int c = 0; c < 32; c++) {
            float v = sP[r][c];
            sre = fmaf(v, twc[t], sre);
            sim = fmaf(-v, tws[t], sim);
            t = (t + k) & 31;
        }
        sYre[r][k] = sre;
        sYim[r][k] = sim;
    }
    __syncthreads();

    const float sl = sigmoidf_(lf[0]);
    const float sm = sigmoidf_(mf[0]);
    const float sh = sigmoidf_(hf[0]);

#pragma unroll
    for (int ii = 0; ii < 4; ii++) {
        int idx = tid + ii * 256;
        int j = idx >> 5, k = idx & 31;
        float fre = 0.f, fim = 0.f;
        int t = 0;
#pragma unroll
        for (int r = 0; r < 32; r++) {
            float cc = twc[t], ss = tws[t];
            float yre = sYre[r][k], yim = sYim[r][k];
            fre = fmaf(yre, cc, fre);
            fre = fmaf(yim, ss, fre);
            fim = fmaf(yim, cc, fim);
            fim = fmaf(-yre, ss, fim);
            t = (t + j) & 31;
        }
        float mag = sqrtf(fre * fre + fim * fim) * 0.03125f;
        float dy = (float)j - 15.5f, dx = (float)k - 15.5f;
        float r2 = dy * dy + dx * dx;
        float gate = (r2 <= 53.388889f) ? sl : ((r2 <= 213.555556f) ? sm : sh);
        float mv = mag * gate;
        g_mag[p * DD + idx] = mv;
        g_magh[p * DD + idx] = __float2bfloat16_rn(mv);
    }
}

// ====================================================================
// bf16 GEMM: BM=128, BN=64, BK=64; 256 threads = 8 warps (4m x 2n),
// warp tile 32x32, mma m16n8k16, 2-stage cp.async, swizzled 48 KB.
// ====================================================================

__device__ __forceinline__ void issue64(uint32_t sb,
                                        const __nv_bfloat16* __restrict__ Agm, int lda,
                                        const __nv_bfloat16* __restrict__ Bgm, int ldb,
                                        int m0, int n0, int k0, int tid) {
    const int r = tid >> 3, ch = tid & 7;
    const int cb = ch << 4;
#pragma unroll
    for (int i = 0; i < 4; i++) {
        int row = r + 32 * i;
        cpa16(sb + swz(row, cb), Agm + (m0 + row) * lda + k0 + ch * 8);
    }
#pragma unroll
    for (int i = 0; i < 2; i++) {
        int row = r + 32 * i;
        cpa16(sb + B_OFF + swz(row, cb), Bgm + (n0 + row) * ldb + k0 + ch * 8);
    }
}

__device__ __forceinline__ void compute64(const char* __restrict__ S,
                                          float acc[2][4][4],
                                          int wm, int wn, int g, int tg) {
#pragma unroll
    for (int ks = 0; ks < 4; ks++) {
        uint32_t af[2][4], bfr[4][2];
        const int byte0 = ks * 32 + tg * 4;
#pragma unroll
        for (int mt = 0; mt < 2; mt++) {
            int r0 = wm * 32 + mt * 16 + g;
            af[mt][0] = *(const uint32_t*)(S + swz(r0, byte0));
            af[mt][1] = *(const uint32_t*)(S + swz(r0 + 8, byte0));
            af[mt][2] = *(const uint32_t*)(S + swz(r0, byte0 + 16));
            af[mt][3] = *(const uint32_t*)(S + swz(r0 + 8, byte0 + 16));
        }
#pragma unroll
        for (int nt = 0; nt < 4; nt++) {
            int rn = wn * 32 + nt * 8 + g;
            bfr[nt][0] = *(const uint32_t*)(S + B_OFF + swz(rn, byte0));
            bfr[nt][1] = *(const uint32_t*)(S + B_OFF + swz(rn, byte0 + 16));
        }
#pragma unroll
        for (int mt = 0; mt < 2; mt++)
#pragma unroll
            for (int nt = 0; nt < 4; nt++) mma16(acc[mt][nt], af[mt], bfr[nt]);
    }
}

// Kernel 2: hidden = relu(mag @ W1 + b1)  M=1024 N=1536 K=1024 (16 tiles)
__global__ __launch_bounds__(256) void k_gemm1(const float* __restrict__ b1) {
    extern __shared__ char smc[];
    const int tid = threadIdx.x;
    const int m0 = blockIdx.x * 128, n0 = blockIdx.y * 64;
    const int warp = tid >> 5, lane = tid & 31;
    const int wm = warp & 3, wn = warp >> 2;
    const int g = lane >> 2, tg = lane & 3;

    float acc[2][4][4];
#pragma unroll
    for (int i = 0; i < 2; i++)
#pragma unroll
        for (int j = 0; j < 4; j++)
#pragma unroll
            for (int e = 0; e < 4; e++) acc[i][j][e] = 0.f;

    const uint32_t sbase = (uint32_t)__cvta_generic_to_shared(smc);

    issue64(sbase, g_magh, 1024, g_w1t, 1024, m0, n0, 0, tid);
    cpa_commit();

    for (int kt = 0; kt < 16; kt++) {
        const int cur = kt & 1;
        if (kt < 15) {
            issue64(sbase + (cur ^ 1) * STAGE_B, g_magh, 1024, g_w1t, 1024,
                    m0, n0, (kt + 1) * 64, tid);
            cpa_commit();
            cpa_wait1();
        } else {
            cpa_wait0();
        }
        __syncthreads();
        compute64(smc + cur * STAGE_B, acc, wm, wn, g, tg);
        __syncthreads();
    }

#pragma unroll
    for (int mt = 0; mt < 2; mt++) {
        int row0 = m0 + wm * 32 + mt * 16 + g;
#pragma unroll
        for (int nt = 0; nt < 4; nt++) {
            int col = n0 + wn * 32 + nt * 8 + tg * 2;
            float bb0 = b1[col], bb1 = b1[col + 1];
            __nv_bfloat162 v0 = __floats2bfloat162_rn(
                fmaxf(acc[mt][nt][0] + bb0, 0.f), fmaxf(acc[mt][nt][1] + bb1, 0.f));
            *reinterpret_cast<__nv_bfloat162*>(&g_hiddenh[row0 * 1536 + col]) = v0;
            __nv_bfloat162 v1 = __floats2bfloat162_rn(
                fmaxf(acc[mt][nt][2] + bb0, 0.f), fmaxf(acc[mt][nt][3] + bb1, 0.f));
            *reinterpret_cast<__nv_bfloat162*>(&g_hiddenh[(row0 + 8) * 1536 + col]) = v1;
        }
    }
}

// Kernel 3: attn = sigmoid(hidden @ W2 + b2); rowsum(mag*attn) -> g_wpart;
// last block (ticket) computes per-patch w + global stats. Zero static smem.
// K=1536 (24 tiles)
__global__ __launch_bounds__(256) void k_gemm2(const float* __restrict__ b2) {
    extern __shared__ char smc[];
    float* smem = reinterpret_cast<float*>(smc);
    const int tid = threadIdx.x;
    const int m0 = blockIdx.x * 128, n0 = blockIdx.y * 64;
    const int warp = tid >> 5, lane = tid & 31;
    const int wm = warp & 3, wn = warp >> 2;
    const int g = lane >> 2, tg = lane & 3;

    float acc[2][4][4];
#pragma unroll
    for (int i = 0; i < 2; i++)
#pragma unroll
        for (int j = 0; j < 4; j++)
#pragma unroll
            for (int e = 0; e < 4; e++) acc[i][j][e] = 0.f;

    const uint32_t sbase = (uint32_t)__cvta_generic_to_shared(smc);

    issue64(sbase, g_hiddenh, 1536, g_w2t, 1536, m0, n0, 0, tid);
    cpa_commit();

    for (int kt = 0; kt < 24; kt++) {
        const int cur = kt & 1;
        if (kt < 23) {
            issue64(sbase + (cur ^ 1) * STAGE_B, g_hiddenh, 1536, g_w2t, 1536,
                    m0, n0, (kt + 1) * 64, tid);
            cpa_commit();
            cpa_wait1();
        } else {
            cpa_wait0();
        }
        __syncthreads();
        compute64(smc + cur * STAGE_B, acc, wm, wn, g, tg);
        __syncthreads();
    }

    // smem overlays (dynamic region; mainloop done, contents dead):
    float*    sRow  = smem;                               // [0,256): 128 rows x 2
    unsigned* sRank = reinterpret_cast<unsigned*>(smem + 256);
    float*    s_ra  = smem + 272;
    float*    s_rb  = smem + 280;

    // epilogue: sigmoid, multiply by fp32 mag, per-row partial sums
    float rs[2][2] = {{0.f, 0.f}, {0.f, 0.f}};
#pragma unroll
    for (int mt = 0; mt < 2; mt++) {
        int row0 = m0 + wm * 32 + mt * 16 + g;
#pragma unroll
        for (int nt = 0; nt < 4; nt++) {
            int col = n0 + wn * 32 + nt * 8 + tg * 2;
            float bb0 = b2[col], bb1 = b2[col + 1];
            rs[mt][0] += g_mag[row0 * 1024 + col]           * sigmoidf_(acc[mt][nt][0] + bb0);
            rs[mt][0] += g_mag[row0 * 1024 + col + 1]       * sigmoidf_(acc[mt][nt][1] + bb1);
            rs[mt][1] += g_mag[(row0 + 8) * 1024 + col]     * sigmoidf_(acc[mt][nt][2] + bb0);
            rs[mt][1] += g_mag[(row0 + 8) * 1024 + col + 1] * sigmoidf_(acc[mt][nt][3] + bb1);
        }
    }
#pragma unroll
    for (int mt = 0; mt < 2; mt++)
#pragma unroll
        for (int hh = 0; hh < 2; hh++) {
            float v = rs[mt][hh];
            v += __shfl_xor_sync(0xffffffffu, v, 1);
            v += __shfl_xor_sync(0xffffffffu, v, 2);
            if (tg == 0) sRow[(wm * 32 + mt * 16 + hh * 8 + g) * 2 + wn] = v;
        }
    __syncthreads();
    if (tid < 128) g_wpart[(m0 + tid) * 16 + blockIdx.y] = sRow[tid * 2] + sRow[tid * 2 + 1];

    // ---- last-block stats: write -> fence -> barrier -> ticket -> barrier ----
    __threadfence();
    __syncthreads();
    if (tid == 0) sRank[0] = atomicAdd(&g_done, 1u);
    __syncthreads();
    if (sRank[0] == 127u) {        // grid is (8,16) = 128 blocks
        if (tid == 0) g_done = 0u; // reset for next graph replay
        float va = 0.f, vb = 0.f;
#pragma unroll
        for (int q = 0; q < 4; q++) {
            int p = tid + q * 256;
            const float4* w4 = reinterpret_cast<const float4*>(&g_wpart[p * 16]);
            float4 a0 = w4[0], a1 = w4[1], a2 = w4[2], a3 = w4[3];
            float s = (a0.x + a0.y + a0.z + a0.w) + (a1.x + a1.y + a1.z + a1.w)
                    + (a2.x + a2.y + a2.z + a2.w) + (a3.x + a3.y + a3.z + a3.w);
            float wf = 1.0f + s * (1.0f / 1024.0f);
            g_wf[p] = wf;
            va += wf * g_psum[p];
            vb += wf * wf * g_psumsq[p];
        }
#pragma unroll
        for (int o = 16; o; o >>= 1) {
            va += __shfl_xor_sync(0xffffffffu, va, o);
            vb += __shfl_xor_sync(0xffffffffu, vb, o);
        }
        if (lane == 0) { s_ra[warp] = va; s_rb[warp] = vb; }
        __syncthreads();
        if (tid == 0) {
            float xa = 0.f, xb = 0.f;
#pragma unroll
            for (int q = 0; q < 8; q++) { xa += s_ra[q]; xb += s_rb[q]; }
            float mu = xa * (1.0f / 1048576.0f);
            float ex2 = xb * (1.0f / 1048576.0f);
            g_stats[0] = mu;
            g_stats[1] = ex2 - mu * mu;
        }
    }
}

// ====================================================================
// Kernel 4: out = relu(s_c*x_rec + o_c) — write-bound, plain float4 stores
// ====================================================================
__global__ __launch_bounds__(256) void k_final(const float* __restrict__ wproj,
                                               const float* __restrict__ gamma,
                                               const float* __restrict__ beta,
                                               float* __restrict__ out) {
    __shared__ float sS[64], sO[64];
    const int tid = threadIdx.x;
    if (tid < 64) {
        float mu = g_stats[0], var = g_stats[1];
        float wp = wproj[tid];
        float sc = gamma[tid] * wp * rsqrtf(fmaf(wp * wp, var, 1e-5f));
        sS[tid] = sc;
        sO[tid] = beta[tid] - sc * mu;
    }
    __syncthreads();

    const int t = blockIdx.x * 256 + tid;
    const int b = t >> 14;
    const int rem = t & 16383;
    const int h = rem >> 6;
    const int w4 = rem & 63;
    const int p = b * 64 + (h >> 5) * 8 + (w4 >> 3);

    float4 xr = *reinterpret_cast<const float4*>(&g_pr[p * DD + (h & 31) * 32 + (w4 & 7) * 4]);
    const float wf = g_wf[p];
    xr.x *= wf; xr.y *= wf; xr.z *= wf; xr.w *= wf;

    float* ob = out + ((size_t)b << 22) + (h << 8) + (w4 << 2);
#pragma unroll 8
    for (int ch = 0; ch < 64; ch++) {
        float s = sS[ch], o = sO[ch];
        float4 v;
        v.x = fmaxf(fmaf(s, xr.x, o), 0.f);
        v.y = fmaxf(fmaf(s, xr.y, o), 0.f);
        v.z = fmaxf(fmaf(s, xr.z, o), 0.f);
        v.w = fmaxf(fmaf(s, xr.w, o), 0.f);
        *reinterpret_cast<float4*>(ob + ((size_t)ch << 16)) = v;
    }
}

// ====================================================================
extern "C" void kernel_launch(void* const* d_in, const int* in_sizes, int n_in,
                              void* d_out, int out_size) {
    (void)in_sizes; (void)n_in; (void)out_size;
    const float* x     = (const float*)d_in[0];
    const float* W1    = (const float*)d_in[1];
    const float* b1    = (const float*)d_in[2];
    const float* W2    = (const float*)d_in[3];
    const float* b2    = (const float*)d_in[4];
    const float* wproj = (const float*)d_in[5];
    const float* gamma = (const float*)d_in[6];
    const float* beta  = (const float*)d_in[7];
    const float* lf    = (const float*)d_in[8];
    const float* mf    = (const float*)d_in[9];
    const float* hf    = (const float*)d_in[10];
    float* out = (float*)d_out;

    k_prep<<<dim3(48, 48, 2), dim3(32, 8)>>>(W1, W2);
    k_fft<<<1024, 256>>>(x, lf, mf, hf);
    k_gemm1<<<dim3(8, 24), 256, GSMEM_BYTES>>>(b1);
    k_gemm2<<<dim3(8, 16), 256, GSMEM_BYTES>>>(b2);
    k_final<<<1024, 256>>>(wproj, gamma, beta, out);
}